// round 11
// baseline (speedup 1.0000x reference)
#include <cuda_runtime.h>
#include <cuda_bf16.h>
#include <math.h>
#include <stdint.h>

// ---------------- problem constants ----------------
#define B_ 128
#define S_ 256
#define H_ 128

// ---------------- device scratch (allocation-free) ----------------
__device__ float g_ET[B_ * 256 * 256];        // [b][n=256][s=256]  E transposed (B-operand of MSG)
__device__ float g_MSG[B_ * S_ * 256];        // [m=32768][256]
__device__ float g_G[B_ * S_ * 512];          // [m][512] = S1 | S2 | i_n | h_n
__device__ float g_H2[B_ * S_ * H_];          // new hidden
__device__ float g_Q12[B_ * S_ * 256];        // [m][256] q1|q2
__device__ float g_WET[256 * 128];            // [n][k]  (W_ein ; W_eout)
__device__ float g_WQT[256 * 128];            // [n][k]  (W_q1 ; W_q2)
__device__ float g_WBT[512 * 384];            // [n][k]  fused GRU weight
__device__ float g_biasE[256];
__device__ float g_biasQ[256];
__device__ float g_biasIO[256];
__device__ float g_biasBig[512];
__device__ float g_q0v[B_ * H_];
__device__ int   g_nvalid[B_];

// ---------------- helpers ----------------
__device__ __forceinline__ uint16_t bfu(__nv_bfloat16 h) {
    return *reinterpret_cast<uint16_t*>(&h);
}

__device__ __forceinline__ void cvt_split(float4 v, uint2& hi, uint2& lo) {
    __nv_bfloat16 h0 = __float2bfloat16_rn(v.x), h1 = __float2bfloat16_rn(v.y);
    __nv_bfloat16 h2 = __float2bfloat16_rn(v.z), h3 = __float2bfloat16_rn(v.w);
    __nv_bfloat16 l0 = __float2bfloat16_rn(v.x - __bfloat162float(h0));
    __nv_bfloat16 l1 = __float2bfloat16_rn(v.y - __bfloat162float(h1));
    __nv_bfloat16 l2 = __float2bfloat16_rn(v.z - __bfloat162float(h2));
    __nv_bfloat16 l3 = __float2bfloat16_rn(v.w - __bfloat162float(h3));
    hi = make_uint2((uint32_t)bfu(h0) | ((uint32_t)bfu(h1) << 16),
                    (uint32_t)bfu(h2) | ((uint32_t)bfu(h3) << 16));
    lo = make_uint2((uint32_t)bfu(l0) | ((uint32_t)bfu(l1) << 16),
                    (uint32_t)bfu(l2) | ((uint32_t)bfu(l3) << 16));
}

#define LDSM4(r, a) \
    asm volatile("ldmatrix.sync.aligned.m8n8.x4.shared.b16 {%0,%1,%2,%3}, [%4];" \
                 : "=r"((r)[0]), "=r"((r)[1]), "=r"((r)[2]), "=r"((r)[3]) : "r"(a))

#define MMA_BF16(c, a, b) \
    asm volatile("mma.sync.aligned.m16n8k16.row.col.f32.bf16.bf16.f32 " \
                 "{%0,%1,%2,%3}, {%4,%5,%6,%7}, {%8,%9}, {%0,%1,%2,%3};" \
                 : "+f"((c)[0]), "+f"((c)[1]), "+f"((c)[2]), "+f"((c)[3]) \
                 : "r"((a)[0]), "r"((a)[1]), "r"((a)[2]), "r"((a)[3]), \
                   "r"((b)[0]), "r"((b)[1]))

// ---------------- weight prep ----------------
__global__ void prep_kernel(const float* __restrict__ w_ih, const float* __restrict__ w_hh,
                            const float* __restrict__ b_ih, const float* __restrict__ b_hh,
                            const float* __restrict__ W_ein, const float* __restrict__ b_ein,
                            const float* __restrict__ W_eout, const float* __restrict__ b_eout,
                            const float* __restrict__ b_iah, const float* __restrict__ b_oah,
                            const float* __restrict__ W_q1, const float* __restrict__ b_q1,
                            const float* __restrict__ W_q2, const float* __restrict__ b_q2) {
    int idx = blockIdx.x * blockDim.x + threadIdx.x;
    if (idx < 512 * 384) {  // g_WBT [n][k]
        int n = idx / 384, k = idx - n * 384;
        float v;
        if (n < 256)      v = (k < 256) ? w_ih[n * 256 + k] : w_hh[n * 128 + (k - 256)];
        else if (n < 384) v = (k < 256) ? w_ih[n * 256 + k] : 0.f;
        else              v = (k >= 256) ? w_hh[(n - 128) * 128 + (k - 256)] : 0.f;
        g_WBT[idx] = v;
    }
    if (idx < 256 * 128) {  // [n][k]
        int n = idx >> 7, k = idx & 127;
        g_WET[idx] = (n < 128) ? W_ein[n * 128 + k] : W_eout[(n - 128) * 128 + k];
        g_WQT[idx] = (n < 128) ? W_q1[n * 128 + k]  : W_q2[(n - 128) * 128 + k];
    }
    if (idx < 512) {
        float bb;
        if (idx < 256)      bb = b_ih[idx] + b_hh[idx];
        else if (idx < 384) bb = b_ih[idx];
        else                bb = b_hh[idx - 128];
        g_biasBig[idx] = bb;
    }
    if (idx < 256) {
        g_biasE[idx]  = (idx < 128) ? b_ein[idx] : b_eout[idx - 128];
        g_biasQ[idx]  = (idx < 128) ? b_q1[idx]  : b_q2[idx - 128];
        g_biasIO[idx] = (idx < 128) ? b_iah[idx] : b_oah[idx - 128];
    }
}

// ---------------- generic bf16x3 warp-MMA GEMM, double-buffered + pipelined ----------------
// C[M,N] = X[M,K] @ Bt[N,K]^T (+bias).  CTA tile 128x128, chunks of K=32.
// MODE 0: E   = hidden @ WET^T        -> g_ET (transposed out, +biasE)
// MODE 1: MSG = A[b] @ ET[b]^T        -> g_MSG (+biasIO)
// MODE 2: G   = [MSG|hidden] @ WBT^T  -> g_G (+biasBig, zero-skip K-ranges)
// MODE 3: Q12 = H2 @ WQT^T            -> g_Q12 (+biasQ)
#define LDS_ 40        // row stride in halfs (80 bytes): conflict-free for STS + ldmatrix
#define BUF_H 20480    // halfs per buffer set (4 planes x 128 x 40)
#define PLANE_H 5120   // halfs per plane
#define GEMM_SMEM (2 * BUF_H * 2)  // 81920 bytes

template<int MODE>
__global__ void __launch_bounds__(256, 2) gemm_mma(const float* __restrict__ Xext) {
    extern __shared__ __align__(16) uint16_t smraw[];
    uint32_t smb = (uint32_t)__cvta_generic_to_shared(&smraw[0]);

    int tid = threadIdx.x;
    int wid = tid >> 5, lane = tid & 31;
    int n0 = blockIdx.x * 128;
    int m0 = blockIdx.y * 128;
    int bz = blockIdx.z;

    const float* Bt; int ldb, K0 = 0, K1, lda, xcol0 = 0;
    const float* Xp;
    if (MODE == 0)      { Bt = g_WET; ldb = 128; K1 = 128; lda = 128; Xp = Xext; }
    else if (MODE == 1) { Bt = g_ET + (size_t)bz * 65536; ldb = 256; K1 = 256; lda = 512;
                          Xp = Xext + (size_t)bz * 131072; xcol0 = (n0 >= 128) ? 256 : 0; }
    else if (MODE == 2) { Bt = g_WBT; ldb = 384; lda = 256; Xp = g_MSG;
                          if (n0 < 256) { K0 = 0; K1 = 384; }
                          else if (n0 == 256) { K0 = 0; K1 = 256; }
                          else { K0 = 256; K1 = 384; } }
    else                { Bt = g_WQT; ldb = 128; K1 = 128; lda = 128; Xp = g_H2; }

    const int wm0 = (wid & 3) * 32;   // warp m-offset in CTA tile
    const int wn0 = (wid >> 2) * 64;  // warp n-offset

    float acc[2][8][4];
#pragma unroll
    for (int i = 0; i < 2; i++)
#pragma unroll
        for (int j = 0; j < 8; j++)
#pragma unroll
            for (int c = 0; c < 4; c++) acc[i][j][c] = 0.f;

    int r8 = tid >> 3;            // 0..31 (row within 32-row pass)
    int c4 = (tid & 7) * 4;       // float col within 32-wide chunk

    // ldmatrix per-lane address components
    int am = lane & 15;
    int akh = (lane >> 4) << 3;
    int bnl = (lane & 7) + ((lane >> 4) << 3);
    int bkh = ((lane >> 3) & 1) << 3;

    float4 xv[4], bv[4];

    // ---- prefetch LDG of one chunk (X + B) into registers ----
    auto ldg_chunk = [&](int kt) {
        const float* Xs = Xp; int ldx = lda; int col = kt + xcol0;
        if (MODE == 2 && kt >= 256) { Xs = Xext; ldx = 128; col = kt - 256; }
#pragma unroll
        for (int p = 0; p < 4; p++)
            xv[p] = *reinterpret_cast<const float4*>(Xs + (size_t)(m0 + p * 32 + r8) * ldx + col + c4);
#pragma unroll
        for (int p = 0; p < 4; p++)
            bv[p] = *reinterpret_cast<const float4*>(Bt + (size_t)(n0 + p * 32 + r8) * ldb + kt + c4);
    };
    // ---- convert + STS prefetched regs into buffer pb ----
    auto sts_chunk = [&](int pb) {
        int bufh = pb * BUF_H;
#pragma unroll
        for (int p = 0; p < 4; p++) {
            uint2 hi, lo;
            cvt_split(xv[p], hi, lo);
            int off = bufh + (p * 32 + r8) * LDS_ + c4;
            *reinterpret_cast<uint2*>(&smraw[off]) = hi;
            *reinterpret_cast<uint2*>(&smraw[off + PLANE_H]) = lo;
        }
#pragma unroll
        for (int p = 0; p < 4; p++) {
            uint2 hi, lo;
            cvt_split(bv[p], hi, lo);
            int off = bufh + 2 * PLANE_H + (p * 32 + r8) * LDS_ + c4;
            *reinterpret_cast<uint2*>(&smraw[off]) = hi;
            *reinterpret_cast<uint2*>(&smraw[off + PLANE_H]) = lo;
        }
    };

    // ---- prologue ----
    ldg_chunk(K0);
    sts_chunk(0);
    __syncthreads();

    int nc = (K1 - K0) >> 5;
    int pb = 0;
    for (int c = 0; c < nc; c++) {
        bool more = (c + 1 < nc);
        if (more) ldg_chunk(K0 + (c + 1) * 32);

        // ---- compute chunk from buffer pb: 2 k-steps of 16 ----
        uint32_t bufb = smb + (uint32_t)(pb * BUF_H * 2);
#pragma unroll
        for (int ks = 0; ks < 32; ks += 16) {
            uint32_t ahi[2][4], alo[2][4];
#pragma unroll
            for (int i = 0; i < 2; i++) {
                uint32_t aoff = bufb + (uint32_t)((wm0 + i * 16 + am) * LDS_ + ks + akh) * 2;
                LDSM4(ahi[i], aoff);
                LDSM4(alo[i], aoff + PLANE_H * 2);
            }
#pragma unroll
            for (int jp = 0; jp < 4; jp++) {
                uint32_t boff = bufb + (uint32_t)(2 * PLANE_H + (wn0 + jp * 16 + bnl) * LDS_ + ks + bkh) * 2;
                uint32_t bh[4], bl[4];
                LDSM4(bh, boff);
                LDSM4(bl, boff + PLANE_H * 2);
#pragma unroll
                for (int i = 0; i < 2; i++) {
#pragma unroll
                    for (int jj = 0; jj < 2; jj++) {
                        float* cc = acc[i][jp * 2 + jj];
                        MMA_BF16(cc, alo[i], (bh + jj * 2));
                        MMA_BF16(cc, ahi[i], (bl + jj * 2));
                        MMA_BF16(cc, ahi[i], (bh + jj * 2));
                    }
                }
            }
        }

        if (more) sts_chunk(pb ^ 1);
        __syncthreads();
        pb ^= 1;
    }

    // ---- epilogue: registers -> gmem with bias ----
    int mrow = m0 + wm0 + (lane >> 2);       // first of the two m-rows per tile
    int ncol = wn0 + (lane & 3) * 2;         // within-CTA n offset (add j*8)
    if (MODE == 0) {
        // out[n*256 + s] transposed
        int b = mrow >> 8, s = mrow & 255;   // same b for s and s+8 within a 128-tile
        float* o = g_ET + (size_t)b * 65536;
#pragma unroll
        for (int i = 0; i < 2; i++) {
            int s0 = s + i * 16;
#pragma unroll
            for (int j = 0; j < 8; j++) {
                int n = n0 + ncol + j * 8;
                float* cc = acc[i][j];
                o[(size_t)n * 256 + s0]           = cc[0] + g_biasE[n];
                o[(size_t)(n + 1) * 256 + s0]     = cc[1] + g_biasE[n + 1];
                o[(size_t)n * 256 + s0 + 8]       = cc[2] + g_biasE[n];
                o[(size_t)(n + 1) * 256 + s0 + 8] = cc[3] + g_biasE[n + 1];
            }
        }
    } else {
        float* out; const float* bias; int ld; size_t rbase;
        if (MODE == 1) { out = g_MSG; bias = g_biasIO; ld = 256; rbase = (size_t)bz * 256 + mrow; }
        else if (MODE == 2) { out = g_G; bias = g_biasBig; ld = 512; rbase = (size_t)mrow; }
        else { out = g_Q12; bias = g_biasQ; ld = 256; rbase = (size_t)mrow; }
#pragma unroll
        for (int i = 0; i < 2; i++) {
            float* o0 = out + (rbase + i * 16) * ld;
            float* o1 = o0 + 8 * ld;
#pragma unroll
            for (int j = 0; j < 8; j++) {
                int n = n0 + ncol + j * 8;
                float* cc = acc[i][j];
                float2 v0 = make_float2(cc[0] + bias[n], cc[1] + bias[n + 1]);
                float2 v1 = make_float2(cc[2] + bias[n], cc[3] + bias[n + 1]);
                *reinterpret_cast<float2*>(o0 + n) = v0;
                *reinterpret_cast<float2*>(o1 + n) = v1;
            }
        }
    }
}

// ---------------- GRU elementwise update ----------------
__global__ void gru_kernel(const float* __restrict__ hidden) {
    int idx = blockIdx.x * blockDim.x + threadIdx.x;
    int m = idx >> 7, j = idx & 127;
    const float* Gm = g_G + (size_t)m * 512;
    float s1 = Gm[j];
    float s2 = Gm[128 + j];
    float in_ = Gm[256 + j];
    float hn = Gm[384 + j];
    float hv = hidden[idx];
    float r = 1.f / (1.f + expf(-s1));
    float z = 1.f / (1.f + expf(-s2));
    float ng = tanhf(in_ + r * hn);
    g_H2[idx] = hv - z * (hv - ng);
}

// ---------------- nvalid + ht1 gather + q0 GEMV ----------------
__global__ void q0_kernel(const int* __restrict__ mask,
                          const float* __restrict__ W_q0, const float* __restrict__ b_q0) {
    __shared__ int ired[128];
    __shared__ float ht[128];
    int b = blockIdx.x, t = threadIdx.x;
    ired[t] = mask[b * 256 + t] + mask[b * 256 + 128 + t];
    __syncthreads();
    for (int off = 64; off; off >>= 1) {
        if (t < off) ired[t] += ired[t + off];
        __syncthreads();
    }
    int nv = ired[0];
    int li = nv - 1;
    ht[t] = g_H2[((size_t)b * 256 + li) * 128 + t];
    __syncthreads();
    float acc = 0.f;
#pragma unroll 8
    for (int k = 0; k < 128; k++) acc += ht[k] * W_q0[t * 128 + k];
    g_q0v[b * 128 + t] = acc + b_q0[t];
    if (t == 0) g_nvalid[b] = nv;
}

// ---------------- collapsed attention readout ----------------
__global__ void attn_kernel(float* __restrict__ out) {
    __shared__ float q0s[128];
    __shared__ float sc[8][256];
    __shared__ float red[256];
    int b = blockIdx.x, t = threadIdx.x;
    const float* Q = g_Q12 + (size_t)b * 256 * 256;
    if (t < 128) q0s[t] = g_q0v[b * 128 + t];
    __syncthreads();
    for (int e = t; e < 2048; e += 256) {
        int h = e >> 8, j = e & 255;
        const float* q1 = Q + j * 256 + h * 16;
        float s = 0.f;
#pragma unroll
        for (int d = 0; d < 16; d++) s += q0s[h * 16 + d] * q1[d];
        sc[h][j] = 1.f / (1.f + expf(-s));
    }
    __syncthreads();
    {
        int w = t >> 5, lane = t & 31;
        float sum = 0.f;
        for (int j = lane; j < 256; j += 32) {
            float e = expf(sc[w][j]);
            sc[w][j] = e;
            sum += e;
        }
#pragma unroll
        for (int o = 16; o; o >>= 1) sum += __shfl_xor_sync(0xFFFFFFFFu, sum, o);
        float inv = 1.f / sum;
        for (int j = lane; j < 256; j += 32) sc[w][j] *= inv;
    }
    __syncthreads();
    {
        int j = t;
        float e[8], s = 0.f;
#pragma unroll
        for (int h = 0; h < 8; h++) { e[h] = expf(2.f * sc[h][j]); s += e[h]; }
        float inv = 1.f / s;
#pragma unroll
        for (int h = 0; h < 8; h++) sc[h][j] = e[h] * inv;
    }
    __syncthreads();
    {
        int o = t & 127, half = t >> 7;
        int h = o >> 4, d = o & 15;
        float acc = 0.f;
        int j0 = half * 128;
        for (int j = j0; j < j0 + 128; j++)
            acc += sc[h][j] * Q[j * 256 + 128 + h * 16 + d];
        red[t] = acc;
    }
    __syncthreads();
    if (t < 128) {
        float y = red[t] + red[t + 128];
        out[b * 128 + t] = (float)g_nvalid[b] * y;
    }
}

// ---------------- launch ----------------
extern "C" void kernel_launch(void* const* d_in, const int* in_sizes, int n_in,
                              void* d_out, int out_size) {
    const float* A      = (const float*)d_in[0];
    const float* hidden = (const float*)d_in[1];
    const int*   mask   = (const int*)d_in[2];
    const float* w_ih   = (const float*)d_in[3];
    const float* w_hh   = (const float*)d_in[4];
    const float* b_ih   = (const float*)d_in[5];
    const float* b_hh   = (const float*)d_in[6];
    const float* b_iah  = (const float*)d_in[7];
    const float* b_oah  = (const float*)d_in[8];
    const float* W_ein  = (const float*)d_in[9];
    const float* b_ein  = (const float*)d_in[10];
    const float* W_eout = (const float*)d_in[11];
    const float* b_eout = (const float*)d_in[12];
    const float* W_q0   = (const float*)d_in[13];
    const float* b_q0   = (const float*)d_in[14];
    const float* W_q1   = (const float*)d_in[15];
    const float* b_q1   = (const float*)d_in[16];
    const float* W_q2   = (const float*)d_in[17];
    const float* b_q2   = (const float*)d_in[18];
    float* out = (float*)d_out;

    static bool attr_done = false;
    if (!attr_done) {
        cudaFuncSetAttribute(gemm_mma<0>, cudaFuncAttributeMaxDynamicSharedMemorySize, GEMM_SMEM);
        cudaFuncSetAttribute(gemm_mma<1>, cudaFuncAttributeMaxDynamicSharedMemorySize, GEMM_SMEM);
        cudaFuncSetAttribute(gemm_mma<2>, cudaFuncAttributeMaxDynamicSharedMemorySize, GEMM_SMEM);
        cudaFuncSetAttribute(gemm_mma<3>, cudaFuncAttributeMaxDynamicSharedMemorySize, GEMM_SMEM);
        attr_done = true;
    }

    // 0) weight prep
    prep_kernel<<<768, 256>>>(w_ih, w_hh, b_ih, b_hh, W_ein, b_ein, W_eout, b_eout,
                              b_iah, b_oah, W_q1, b_q1, W_q2, b_q2);
    // 1) E^T = (hidden @ WET^T)^T + biasE      -> g_ET
    gemm_mma<0><<<dim3(2, 256, 1), 256, GEMM_SMEM>>>(hidden);
    // 2) MSG = A @ E + biasIO (batched)        -> g_MSG
    gemm_mma<1><<<dim3(2, 2, 128), 256, GEMM_SMEM>>>(A);
    // 3) G = [MSG|hidden] @ WBT^T + biasBig    -> g_G   (zero-skip K-ranges)
    gemm_mma<2><<<dim3(4, 256, 1), 256, GEMM_SMEM>>>(hidden);
    // 4) GRU update -> g_H2
    gru_kernel<<<16384, 256>>>(hidden);
    // 5) nvalid, ht1, q0
    q0_kernel<<<128, 128>>>(mask, W_q0, b_q0);
    // 6) Q12 = H2 @ WQT^T + biasQ -> g_Q12
    gemm_mma<3><<<dim3(2, 256, 1), 256, GEMM_SMEM>>>(nullptr);
    // 7) collapsed attention + readout
    attn_kernel<<<128, 256>>>(out);
}

// round 12
// speedup vs baseline: 1.5910x; 1.5910x over previous
#include <cuda_runtime.h>
#include <cuda_fp16.h>
#include <math.h>
#include <stdint.h>

// ---------------- problem constants ----------------
#define B_ 128
#define S_ 256
#define H_ 128

// ---------------- device scratch (allocation-free) ----------------
__device__ float g_ET[B_ * 256 * 256];        // [b][n=256][s=256]  E transposed (B-operand of MSG)
__device__ float g_MSG[B_ * S_ * 256];        // [m=32768][256]
__device__ float g_G[B_ * S_ * 512];          // [m][512] = S1 | S2 | i_n | h_n
__device__ float g_H2[B_ * S_ * H_];          // new hidden
__device__ float g_Q12[B_ * S_ * 256];        // [m][256] q1|q2
__device__ float g_WET[256 * 128];            // [n][k]  (W_ein ; W_eout)
__device__ float g_WQT[256 * 128];            // [n][k]  (W_q1 ; W_q2)
__device__ float g_WBT[512 * 384];            // [n][k]  fused GRU weight
__device__ float g_biasE[256];
__device__ float g_biasQ[256];
__device__ float g_biasIO[256];
__device__ float g_biasBig[512];
__device__ float g_q0v[B_ * H_];
__device__ int   g_nvalid[B_];

// ---------------- helpers ----------------
__device__ __forceinline__ uint2 cvt_pack_f16(float4 v) {
    __half2 a = __floats2half2_rn(v.x, v.y);
    __half2 b = __floats2half2_rn(v.z, v.w);
    return make_uint2(*reinterpret_cast<uint32_t*>(&a), *reinterpret_cast<uint32_t*>(&b));
}

#define LDSM4(r, a) \
    asm volatile("ldmatrix.sync.aligned.m8n8.x4.shared.b16 {%0,%1,%2,%3}, [%4];" \
                 : "=r"((r)[0]), "=r"((r)[1]), "=r"((r)[2]), "=r"((r)[3]) : "r"(a))

#define MMA_F16(c, a, b) \
    asm volatile("mma.sync.aligned.m16n8k16.row.col.f32.f16.f16.f32 " \
                 "{%0,%1,%2,%3}, {%4,%5,%6,%7}, {%8,%9}, {%0,%1,%2,%3};" \
                 : "+f"((c)[0]), "+f"((c)[1]), "+f"((c)[2]), "+f"((c)[3]) \
                 : "r"((a)[0]), "r"((a)[1]), "r"((a)[2]), "r"((a)[3]), \
                   "r"((b)[0]), "r"((b)[1]))

// ---------------- weight prep ----------------
__global__ void prep_kernel(const float* __restrict__ w_ih, const float* __restrict__ w_hh,
                            const float* __restrict__ b_ih, const float* __restrict__ b_hh,
                            const float* __restrict__ W_ein, const float* __restrict__ b_ein,
                            const float* __restrict__ W_eout, const float* __restrict__ b_eout,
                            const float* __restrict__ b_iah, const float* __restrict__ b_oah,
                            const float* __restrict__ W_q1, const float* __restrict__ b_q1,
                            const float* __restrict__ W_q2, const float* __restrict__ b_q2) {
    int idx = blockIdx.x * blockDim.x + threadIdx.x;
    if (idx < 512 * 384) {  // g_WBT [n][k]
        int n = idx / 384, k = idx - n * 384;
        float v;
        if (n < 256)      v = (k < 256) ? w_ih[n * 256 + k] : w_hh[n * 128 + (k - 256)];
        else if (n < 384) v = (k < 256) ? w_ih[n * 256 + k] : 0.f;
        else              v = (k >= 256) ? w_hh[(n - 128) * 128 + (k - 256)] : 0.f;
        g_WBT[idx] = v;
    }
    if (idx < 256 * 128) {  // [n][k]
        int n = idx >> 7, k = idx & 127;
        g_WET[idx] = (n < 128) ? W_ein[n * 128 + k] : W_eout[(n - 128) * 128 + k];
        g_WQT[idx] = (n < 128) ? W_q1[n * 128 + k]  : W_q2[(n - 128) * 128 + k];
    }
    if (idx < 512) {
        float bb;
        if (idx < 256)      bb = b_ih[idx] + b_hh[idx];
        else if (idx < 384) bb = b_ih[idx];
        else                bb = b_hh[idx - 128];
        g_biasBig[idx] = bb;
    }
    if (idx < 256) {
        g_biasE[idx]  = (idx < 128) ? b_ein[idx] : b_eout[idx - 128];
        g_biasQ[idx]  = (idx < 128) ? b_q1[idx]  : b_q2[idx - 128];
        g_biasIO[idx] = (idx < 128) ? b_iah[idx] : b_oah[idx - 128];
    }
}

// ---------------- generic fp16 warp-MMA GEMM, double-buffered + pipelined ----------------
// C[M,N] = X[M,K] @ Bt[N,K]^T (+bias).  CTA tile 128x128, chunks of K=32.
// MODE 0: E   = hidden @ WET^T        -> g_ET (transposed out, +biasE)
// MODE 1: MSG = A[b] @ ET[b]^T        -> g_MSG (+biasIO)
// MODE 2: G   = [MSG|hidden] @ WBT^T  -> g_G (+biasBig, zero-skip K-ranges)
// MODE 3: Q12 = H2 @ WQT^T            -> g_Q12 (+biasQ)
#define LDS_ 40        // row stride in halfs (80 bytes): conflict-free for STS + ldmatrix
#define PLANE_H 5120   // halfs per plane (128 rows x 40)

template<int MODE>
__global__ void __launch_bounds__(256, 2) gemm_mma(const float* __restrict__ Xext) {
    __shared__ __align__(16) uint16_t smraw[2][2 * PLANE_H];  // [buf][X|B plane]  40KB
    uint32_t smb = (uint32_t)__cvta_generic_to_shared(&smraw[0][0]);

    int tid = threadIdx.x;
    int wid = tid >> 5, lane = tid & 31;
    int n0 = blockIdx.x * 128;
    int m0 = blockIdx.y * 128;
    int bz = blockIdx.z;

    const float* Bt; int ldb, K0 = 0, K1, lda, xcol0 = 0;
    const float* Xp;
    if (MODE == 0)      { Bt = g_WET; ldb = 128; K1 = 128; lda = 128; Xp = Xext; }
    else if (MODE == 1) { Bt = g_ET + (size_t)bz * 65536; ldb = 256; K1 = 256; lda = 512;
                          Xp = Xext + (size_t)bz * 131072; xcol0 = (n0 >= 128) ? 256 : 0; }
    else if (MODE == 2) { Bt = g_WBT; ldb = 384; lda = 256; Xp = g_MSG;
                          if (n0 < 256) { K0 = 0; K1 = 384; }
                          else if (n0 == 256) { K0 = 0; K1 = 256; }
                          else { K0 = 256; K1 = 384; } }
    else                { Bt = g_WQT; ldb = 128; K1 = 128; lda = 128; Xp = g_H2; }

    const int wm0 = (wid & 3) * 32;   // warp m-offset in CTA tile
    const int wn0 = (wid >> 2) * 64;  // warp n-offset

    float acc[2][8][4];
#pragma unroll
    for (int i = 0; i < 2; i++)
#pragma unroll
        for (int j = 0; j < 8; j++)
#pragma unroll
            for (int c = 0; c < 4; c++) acc[i][j][c] = 0.f;

    int r8 = tid >> 3;            // 0..31 (row within 32-row pass)
    int c4 = (tid & 7) * 4;       // float col within 32-wide chunk

    // ldmatrix per-lane address components
    int am = lane & 15;
    int akh = (lane >> 4) << 3;
    int bnl = (lane & 7) + ((lane >> 4) << 3);
    int bkh = ((lane >> 3) & 1) << 3;

    float4 xv[4], bv[4];

    // ---- prefetch LDG of one chunk (X + B) into registers ----
    auto ldg_chunk = [&](int kt) {
        const float* Xs = Xp; int ldx = lda; int col = kt + xcol0;
        if (MODE == 2 && kt >= 256) { Xs = Xext; ldx = 128; col = kt - 256; }
#pragma unroll
        for (int p = 0; p < 4; p++)
            xv[p] = *reinterpret_cast<const float4*>(Xs + (size_t)(m0 + p * 32 + r8) * ldx + col + c4);
#pragma unroll
        for (int p = 0; p < 4; p++)
            bv[p] = *reinterpret_cast<const float4*>(Bt + (size_t)(n0 + p * 32 + r8) * ldb + kt + c4);
    };
    // ---- convert + STS prefetched regs into buffer pb ----
    auto sts_chunk = [&](int pb) {
#pragma unroll
        for (int p = 0; p < 4; p++) {
            int off = (p * 32 + r8) * LDS_ + c4;
            *reinterpret_cast<uint2*>(&smraw[pb][off]) = cvt_pack_f16(xv[p]);
            *reinterpret_cast<uint2*>(&smraw[pb][off + PLANE_H]) = cvt_pack_f16(bv[p]);
        }
    };

    // ---- prologue ----
    ldg_chunk(K0);
    sts_chunk(0);
    __syncthreads();

    int nc = (K1 - K0) >> 5;
    int pb = 0;
    for (int c = 0; c < nc; c++) {
        bool more = (c + 1 < nc);
        if (more) ldg_chunk(K0 + (c + 1) * 32);

        // ---- compute chunk from buffer pb: 2 k-steps of 16 ----
        uint32_t bufb = smb + (uint32_t)(pb * 2 * PLANE_H * 2);
#pragma unroll
        for (int ks = 0; ks < 32; ks += 16) {
            uint32_t af[2][4];
#pragma unroll
            for (int i = 0; i < 2; i++) {
                uint32_t aoff = bufb + (uint32_t)((wm0 + i * 16 + am) * LDS_ + ks + akh) * 2;
                LDSM4(af[i], aoff);
            }
#pragma unroll
            for (int jp = 0; jp < 4; jp++) {
                uint32_t boff = bufb + (uint32_t)(PLANE_H + (wn0 + jp * 16 + bnl) * LDS_ + ks + bkh) * 2;
                uint32_t bf[4];
                LDSM4(bf, boff);
#pragma unroll
                for (int i = 0; i < 2; i++) {
#pragma unroll
                    for (int jj = 0; jj < 2; jj++) {
                        MMA_F16(acc[i][jp * 2 + jj], af[i], (bf + jj * 2));
                    }
                }
            }
        }

        if (more) sts_chunk(pb ^ 1);
        __syncthreads();
        pb ^= 1;
    }

    // ---- epilogue: registers -> gmem with bias ----
    int mrow = m0 + wm0 + (lane >> 2);       // first of the two m-rows per tile
    int ncol = wn0 + (lane & 3) * 2;         // within-CTA n offset (add j*8)
    if (MODE == 0) {
        // out[n*256 + s] transposed
        int b = mrow >> 8, s = mrow & 255;   // same b for s and s+8 within a 128-tile
        float* o = g_ET + (size_t)b * 65536;
#pragma unroll
        for (int i = 0; i < 2; i++) {
            int s0 = s + i * 16;
#pragma unroll
            for (int j = 0; j < 8; j++) {
                int n = n0 + ncol + j * 8;
                float* cc = acc[i][j];
                o[(size_t)n * 256 + s0]           = cc[0] + g_biasE[n];
                o[(size_t)(n + 1) * 256 + s0]     = cc[1] + g_biasE[n + 1];
                o[(size_t)n * 256 + s0 + 8]       = cc[2] + g_biasE[n];
                o[(size_t)(n + 1) * 256 + s0 + 8] = cc[3] + g_biasE[n + 1];
            }
        }
    } else {
        float* out; const float* bias; int ld; size_t rbase;
        if (MODE == 1) { out = g_MSG; bias = g_biasIO; ld = 256; rbase = (size_t)bz * 256 + mrow; }
        else if (MODE == 2) { out = g_G; bias = g_biasBig; ld = 512; rbase = (size_t)mrow; }
        else { out = g_Q12; bias = g_biasQ; ld = 256; rbase = (size_t)mrow; }
#pragma unroll
        for (int i = 0; i < 2; i++) {
            float* o0 = out + (rbase + i * 16) * ld;
            float* o1 = o0 + 8 * ld;
#pragma unroll
            for (int j = 0; j < 8; j++) {
                int n = n0 + ncol + j * 8;
                float* cc = acc[i][j];
                float2 v0 = make_float2(cc[0] + bias[n], cc[1] + bias[n + 1]);
                float2 v1 = make_float2(cc[2] + bias[n], cc[3] + bias[n + 1]);
                *reinterpret_cast<float2*>(o0 + n) = v0;
                *reinterpret_cast<float2*>(o1 + n) = v1;
            }
        }
    }
}

// ---------------- GRU elementwise update ----------------
__global__ void gru_kernel(const float* __restrict__ hidden) {
    int idx = blockIdx.x * blockDim.x + threadIdx.x;
    int m = idx >> 7, j = idx & 127;
    const float* Gm = g_G + (size_t)m * 512;
    float s1 = Gm[j];
    float s2 = Gm[128 + j];
    float in_ = Gm[256 + j];
    float hn = Gm[384 + j];
    float hv = hidden[idx];
    float r = 1.f / (1.f + expf(-s1));
    float z = 1.f / (1.f + expf(-s2));
    float ng = tanhf(in_ + r * hn);
    g_H2[idx] = hv - z * (hv - ng);
}

// ---------------- nvalid + ht1 gather + q0 GEMV ----------------
__global__ void q0_kernel(const int* __restrict__ mask,
                          const float* __restrict__ W_q0, const float* __restrict__ b_q0) {
    __shared__ int ired[128];
    __shared__ float ht[128];
    int b = blockIdx.x, t = threadIdx.x;
    ired[t] = mask[b * 256 + t] + mask[b * 256 + 128 + t];
    __syncthreads();
    for (int off = 64; off; off >>= 1) {
        if (t < off) ired[t] += ired[t + off];
        __syncthreads();
    }
    int nv = ired[0];
    int li = nv - 1;
    ht[t] = g_H2[((size_t)b * 256 + li) * 128 + t];
    __syncthreads();
    float acc = 0.f;
#pragma unroll 8
    for (int k = 0; k < 128; k++) acc += ht[k] * W_q0[t * 128 + k];
    g_q0v[b * 128 + t] = acc + b_q0[t];
    if (t == 0) g_nvalid[b] = nv;
}

// ---------------- collapsed attention readout ----------------
__global__ void attn_kernel(float* __restrict__ out) {
    __shared__ float q0s[128];
    __shared__ float sc[8][256];
    __shared__ float red[256];
    int b = blockIdx.x, t = threadIdx.x;
    const float* Q = g_Q12 + (size_t)b * 256 * 256;
    if (t < 128) q0s[t] = g_q0v[b * 128 + t];
    __syncthreads();
    for (int e = t; e < 2048; e += 256) {
        int h = e >> 8, j = e & 255;
        const float* q1 = Q + j * 256 + h * 16;
        float s = 0.f;
#pragma unroll
        for (int d = 0; d < 16; d++) s += q0s[h * 16 + d] * q1[d];
        sc[h][j] = 1.f / (1.f + expf(-s));
    }
    __syncthreads();
    {
        int w = t >> 5, lane = t & 31;
        float sum = 0.f;
        for (int j = lane; j < 256; j += 32) {
            float e = expf(sc[w][j]);
            sc[w][j] = e;
            sum += e;
        }
#pragma unroll
        for (int o = 16; o; o >>= 1) sum += __shfl_xor_sync(0xFFFFFFFFu, sum, o);
        float inv = 1.f / sum;
        for (int j = lane; j < 256; j += 32) sc[w][j] *= inv;
    }
    __syncthreads();
    {
        int j = t;
        float e[8], s = 0.f;
#pragma unroll
        for (int h = 0; h < 8; h++) { e[h] = expf(2.f * sc[h][j]); s += e[h]; }
        float inv = 1.f / s;
#pragma unroll
        for (int h = 0; h < 8; h++) sc[h][j] = e[h] * inv;
    }
    __syncthreads();
    {
        int o = t & 127, half = t >> 7;
        int h = o >> 4, d = o & 15;
        float acc = 0.f;
        int j0 = half * 128;
        for (int j = j0; j < j0 + 128; j++)
            acc += sc[h][j] * Q[j * 256 + 128 + h * 16 + d];
        red[t] = acc;
    }
    __syncthreads();
    if (t < 128) {
        float y = red[t] + red[t + 128];
        out[b * 128 + t] = (float)g_nvalid[b] * y;
    }
}

// ---------------- launch ----------------
extern "C" void kernel_launch(void* const* d_in, const int* in_sizes, int n_in,
                              void* d_out, int out_size) {
    const float* A      = (const float*)d_in[0];
    const float* hidden = (const float*)d_in[1];
    const int*   mask   = (const int*)d_in[2];
    const float* w_ih   = (const float*)d_in[3];
    const float* w_hh   = (const float*)d_in[4];
    const float* b_ih   = (const float*)d_in[5];
    const float* b_hh   = (const float*)d_in[6];
    const float* b_iah  = (const float*)d_in[7];
    const float* b_oah  = (const float*)d_in[8];
    const float* W_ein  = (const float*)d_in[9];
    const float* b_ein  = (const float*)d_in[10];
    const float* W_eout = (const float*)d_in[11];
    const float* b_eout = (const float*)d_in[12];
    const float* W_q0   = (const float*)d_in[13];
    const float* b_q0   = (const float*)d_in[14];
    const float* W_q1   = (const float*)d_in[15];
    const float* b_q1   = (const float*)d_in[16];
    const float* W_q2   = (const float*)d_in[17];
    const float* b_q2   = (const float*)d_in[18];
    float* out = (float*)d_out;

    // 0) weight prep
    prep_kernel<<<768, 256>>>(w_ih, w_hh, b_ih, b_hh, W_ein, b_ein, W_eout, b_eout,
                              b_iah, b_oah, W_q1, b_q1, W_q2, b_q2);
    // 1) E^T = (hidden @ WET^T)^T + biasE      -> g_ET
    gemm_mma<0><<<dim3(2, 256, 1), 256>>>(hidden);
    // 2) MSG = A @ E + biasIO (batched)        -> g_MSG
    gemm_mma<1><<<dim3(2, 2, 128), 256>>>(A);
    // 3) G = [MSG|hidden] @ WBT^T + biasBig    -> g_G   (zero-skip K-ranges)
    gemm_mma<2><<<dim3(4, 256, 1), 256>>>(hidden);
    // 4) GRU update -> g_H2
    gru_kernel<<<16384, 256>>>(hidden);
    // 5) nvalid, ht1, q0
    q0_kernel<<<128, 128>>>(mask, W_q0, b_q0);
    // 6) Q12 = H2 @ WQT^T + biasQ -> g_Q12
    gemm_mma<3><<<dim3(2, 256, 1), 256>>>(nullptr);
    // 7) collapsed attention + readout
    attn_kernel<<<128, 256>>>(out);
}